// round 2
// baseline (speedup 1.0000x reference)
#include <cuda_runtime.h>

#define NMAX 100000
#define EMAX 1700000
#define KIN  500
#define HID  32
#define NCLS 40

// ---------------- scratch (static __device__, no allocs allowed) ----------------
__device__ float g_h1[NMAX * HID];
__device__ float g_h2[NMAX * HID];
__device__ float g_inv[NMAX];
__device__ int   g_deg[NMAX];
__device__ int   g_rowptr[NMAX + 1];
__device__ int   g_cursor[NMAX];
__device__ int   g_col[EMAX];
__device__ int   g_bsum[256];
__device__ int   g_is64;

typedef unsigned long long ull;

__device__ __forceinline__ ull fma2(ull a, ull b, ull c) {
    ull d;
    asm("fma.rn.f32x2 %0, %1, %2, %3;" : "=l"(d) : "l"(a), "l"(b), "l"(c));
    return d;
}
__device__ __forceinline__ ull dup2(float v) {
    ull r;
    asm("mov.b64 %0, {%1, %1};" : "=l"(r) : "f"(v));
    return r;
}
__device__ __forceinline__ void unp2(ull v, float& lo, float& hi) {
    asm("mov.b64 {%0, %1}, %2;" : "=f"(lo), "=f"(hi) : "l"(v));
}

// ---------------- edge dtype sniff: int64 vs int32 ----------------
// int64 values < 2^31 -> every odd 32-bit word is 0. int32 edge ids are
// random in [0, N); 256 consecutive odd words all zero is impossible.
__global__ void k_detect(const int* __restrict__ w) {
    int v = 0;
    for (int i = threadIdx.x; i < 256; i += 32) v |= w[2 * i + 1];
    #pragma unroll
    for (int o = 16; o; o >>= 1) v |= __shfl_xor_sync(0xffffffffu, v, o);
    if (threadIdx.x == 0) g_is64 = (v == 0) ? 1 : 0;
}

__device__ __forceinline__ int edge_at(const void* ei, long long idx) {
    if (g_is64) return (int)((const long long*)ei)[idx];
    return ((const int*)ei)[idx];
}

// ---------------- GEMM1: h1 = relu(x @ W1 + b1) ----------------
// Block: 256 threads, tile 128 rows x 32 cols, BK=32.
// Thread: 4 rows x 4 cols = 16 outputs, rows packed in pairs as f32x2.
__global__ __launch_bounds__(256) void k_gemm1(const float* __restrict__ x,
                                               const float* __restrict__ W1,
                                               const float* __restrict__ b1,
                                               int n) {
    __shared__ __align__(16) float xs[32 * 130];  // [k][row] transposed, even pad
    __shared__ __align__(16) float wt[32 * 32];   // [k][col]

    const int tid = threadIdx.x;
    const int cg  = tid & 7;    // col group: cols cg*4..+3
    const int rg  = tid >> 3;   // row group: rows rg*4..+3 (0..31)
    const int rowBase = blockIdx.x * 128;

    ull a00 = 0, a01 = 0, a02 = 0, a03 = 0;
    ull a10 = 0, a11 = 0, a12 = 0, a13 = 0;

    for (int k0 = 0; k0 < KIN; k0 += 32) {
        // stage W tile [32][32], zero-padded past K
        #pragma unroll
        for (int q = 0; q < 4; ++q) {
            int idx = tid + q * 256;          // 0..1023
            int kk = idx >> 5, c = idx & 31;
            float w = 0.f;
            if (k0 + kk < KIN) w = W1[(k0 + kk) * HID + c];
            wt[idx] = w;
        }
        // stage x tile transposed, zero-padded (rows >= n or k >= K -> 0)
        #pragma unroll
        for (int q = 0; q < 4; ++q) {
            int r = rg + q * 32;              // staging row 0..127
            int grow = rowBase + r;
            int gk = k0 + cg * 4;
            float4 v = make_float4(0.f, 0.f, 0.f, 0.f);
            if (grow < n && gk < KIN)
                v = *(const float4*)(x + (size_t)grow * KIN + gk);
            xs[(cg * 4 + 0) * 130 + r] = v.x;
            xs[(cg * 4 + 1) * 130 + r] = v.y;
            xs[(cg * 4 + 2) * 130 + r] = v.z;
            xs[(cg * 4 + 3) * 130 + r] = v.w;
        }
        __syncthreads();

        #pragma unroll 16
        for (int kk = 0; kk < 32; ++kk) {
            float4 w4 = *(const float4*)(wt + kk * 32 + cg * 4);
            ull xa = *(const ull*)(xs + kk * 130 + rg * 4);
            ull xb = *(const ull*)(xs + kk * 130 + rg * 4 + 2);
            ull w0 = dup2(w4.x), w1 = dup2(w4.y), w2 = dup2(w4.z), w3 = dup2(w4.w);
            a00 = fma2(xa, w0, a00); a01 = fma2(xa, w1, a01);
            a02 = fma2(xa, w2, a02); a03 = fma2(xa, w3, a03);
            a10 = fma2(xb, w0, a10); a11 = fma2(xb, w1, a11);
            a12 = fma2(xb, w2, a12); a13 = fma2(xb, w3, a13);
        }
        __syncthreads();
    }

    // epilogue: bias + relu + store
    float bc[4];
    #pragma unroll
    for (int c = 0; c < 4; ++c) bc[c] = b1[cg * 4 + c];

    float r0[4], r1[4], r2[4], r3[4];
    unp2(a00, r0[0], r1[0]); unp2(a01, r0[1], r1[1]);
    unp2(a02, r0[2], r1[2]); unp2(a03, r0[3], r1[3]);
    unp2(a10, r2[0], r3[0]); unp2(a11, r2[1], r3[1]);
    unp2(a12, r2[2], r3[2]); unp2(a13, r2[3], r3[3]);

    int base = rowBase + rg * 4;
    float* rows[4] = {r0, r1, r2, r3};
    #pragma unroll
    for (int i = 0; i < 4; ++i) {
        int row = base + i;
        if (row < n) {
            float4 o;
            o.x = fmaxf(rows[i][0] + bc[0], 0.f);
            o.y = fmaxf(rows[i][1] + bc[1], 0.f);
            o.z = fmaxf(rows[i][2] + bc[2], 0.f);
            o.w = fmaxf(rows[i][3] + bc[3], 0.f);
            *(float4*)(g_h1 + (size_t)row * HID + cg * 4) = o;
        }
    }
}

// ---------------- per-node inverse L2 norm ----------------
__global__ void k_norm(int n, int which) {
    const float* h = which ? g_h2 : g_h1;
    int gid = blockIdx.x * blockDim.x + threadIdx.x;
    int node = gid >> 3, fid = gid & 7;
    if (node >= n) return;
    float4 v = *(const float4*)(h + (size_t)node * HID + fid * 4);
    float ss = v.x * v.x + v.y * v.y + v.z * v.z + v.w * v.w;
    ss += __shfl_xor_sync(0xffffffffu, ss, 1);
    ss += __shfl_xor_sync(0xffffffffu, ss, 2);
    ss += __shfl_xor_sync(0xffffffffu, ss, 4);
    if (fid == 0) g_inv[node] = rsqrtf(ss + 1e-12f);
}

// ---------------- CSR build ----------------
__global__ void k_zero(int n) {
    int i = blockIdx.x * blockDim.x + threadIdx.x;
    if (i < n) g_deg[i] = 0;
}

__global__ void k_hist(const void* __restrict__ ei, int E) {
    for (int e = blockIdx.x * blockDim.x + threadIdx.x; e < E;
         e += gridDim.x * blockDim.x) {
        int dst = edge_at(ei, (long long)E + e);
        atomicAdd(&g_deg[dst], 1);
    }
}

__global__ void k_scan1(int n) {
    __shared__ int s[1024];
    int i = blockIdx.x * 1024 + threadIdx.x;
    int v = (i < n) ? g_deg[i] : 0;
    s[threadIdx.x] = v;
    __syncthreads();
    for (int off = 1; off < 1024; off <<= 1) {
        int t = (threadIdx.x >= off) ? s[threadIdx.x - off] : 0;
        __syncthreads();
        s[threadIdx.x] += t;
        __syncthreads();
    }
    if (i < n) g_rowptr[i + 1] = s[threadIdx.x];
    if (threadIdx.x == 1023) g_bsum[blockIdx.x] = s[1023];
}

__global__ void k_scan2(int nb) {
    __shared__ int s[256];
    int t = threadIdx.x;
    int v = (t < nb) ? g_bsum[t] : 0;
    s[t] = v;
    __syncthreads();
    for (int off = 1; off < 256; off <<= 1) {
        int u = (t >= off) ? s[t - off] : 0;
        __syncthreads();
        s[t] += u;
        __syncthreads();
    }
    if (t < nb) g_bsum[t] = (t == 0) ? 0 : s[t - 1];
}

__global__ void k_scan3(int n) {
    int i = blockIdx.x * blockDim.x + threadIdx.x;
    if (i == 0) g_rowptr[0] = 0;
    if (i < n) g_rowptr[i + 1] += g_bsum[i >> 10];
}

__global__ void k_cursor(int n) {
    int i = blockIdx.x * blockDim.x + threadIdx.x;
    if (i < n) g_cursor[i] = g_rowptr[i];
}

__global__ void k_scatter(const void* __restrict__ ei, int E) {
    for (int e = blockIdx.x * blockDim.x + threadIdx.x; e < E;
         e += gridDim.x * blockDim.x) {
        int src = edge_at(ei, e);
        int dst = edge_at(ei, (long long)E + e);
        int p = atomicAdd(&g_cursor[dst], 1);
        g_col[p] = src;
    }
}

// ---------------- AGNN conv (gather): warp per dst, 4 edge-slots x 8 feat-lanes ----------------
__global__ __launch_bounds__(256) void k_conv(int n, const float* __restrict__ beta_ptr,
                                              int dir) {
    const float* hin = dir ? g_h2 : g_h1;
    float* hout      = dir ? g_h1 : g_h2;

    int wid = (blockIdx.x * blockDim.x + threadIdx.x) >> 5;
    if (wid >= n) return;
    int lane = threadIdx.x & 31;
    int sub = lane >> 3;   // edge slot 0..3
    int fid = lane & 7;    // feature group: 4*fid..4*fid+3

    float beta = beta_ptr ? *beta_ptr : 1.0f;
    int dst = wid;
    float4 hd = *(const float4*)(hin + (size_t)dst * HID + fid * 4);
    float cb = beta * g_inv[dst];
    int s = g_rowptr[dst], e = g_rowptr[dst + 1];

    float ax = 0.f, ay = 0.f, az = 0.f, aw = 0.f, ssum = 0.f;
    int nit = (e - s + 3) >> 2;
    for (int it = 0; it < nit; ++it) {
        int p = s + it * 4 + sub;
        bool valid = p < e;
        int src = valid ? g_col[p] : dst;
        float4 hs = *(const float4*)(hin + (size_t)src * HID + fid * 4);
        float invs = g_inv[src];
        float d = hs.x * hd.x + hs.y * hd.y + hs.z * hd.z + hs.w * hd.w;
        d += __shfl_xor_sync(0xffffffffu, d, 1);
        d += __shfl_xor_sync(0xffffffffu, d, 2);
        d += __shfl_xor_sync(0xffffffffu, d, 4);
        float w = valid ? __expf(cb * invs * d) : 0.f;
        ax = fmaf(w, hs.x, ax);
        ay = fmaf(w, hs.y, ay);
        az = fmaf(w, hs.z, az);
        aw = fmaf(w, hs.w, aw);
        ssum += w;
    }
    ax += __shfl_xor_sync(0xffffffffu, ax, 8);  ax += __shfl_xor_sync(0xffffffffu, ax, 16);
    ay += __shfl_xor_sync(0xffffffffu, ay, 8);  ay += __shfl_xor_sync(0xffffffffu, ay, 16);
    az += __shfl_xor_sync(0xffffffffu, az, 8);  az += __shfl_xor_sync(0xffffffffu, az, 16);
    aw += __shfl_xor_sync(0xffffffffu, aw, 8);  aw += __shfl_xor_sync(0xffffffffu, aw, 16);
    ssum += __shfl_xor_sync(0xffffffffu, ssum, 8);
    ssum += __shfl_xor_sync(0xffffffffu, ssum, 16);

    if (sub == 0) {
        float r = 1.f / (ssum + 1e-16f);
        float4 o = make_float4(ax * r, ay * r, az * r, aw * r);
        *(float4*)(hout + (size_t)dst * HID + fid * 4) = o;
    }
}

// ---------------- GEMM2: out = h1 @ W2 + b2 ----------------
__global__ __launch_bounds__(128) void k_gemm2(const float* __restrict__ W2,
                                               const float* __restrict__ b2,
                                               float* __restrict__ out, int n) {
    __shared__ __align__(16) float ws[HID * NCLS];
    __shared__ float bs[NCLS];
    for (int i = threadIdx.x; i < HID * NCLS; i += 128) ws[i] = W2[i];
    if (threadIdx.x < NCLS) bs[threadIdx.x] = b2[threadIdx.x];
    __syncthreads();

    int node = blockIdx.x * blockDim.x + threadIdx.x;
    if (node >= n) return;

    float xr[HID];
    #pragma unroll
    for (int q = 0; q < 8; ++q) {
        float4 v = *(const float4*)(g_h1 + (size_t)node * HID + q * 4);
        xr[q * 4 + 0] = v.x; xr[q * 4 + 1] = v.y;
        xr[q * 4 + 2] = v.z; xr[q * 4 + 3] = v.w;
    }
    float acc[NCLS];
    #pragma unroll
    for (int c = 0; c < NCLS; ++c) acc[c] = bs[c];
    #pragma unroll 8
    for (int k = 0; k < HID; ++k) {
        float xv = xr[k];
        #pragma unroll
        for (int c = 0; c < NCLS; ++c) acc[c] = fmaf(xv, ws[k * NCLS + c], acc[c]);
    }
    #pragma unroll
    for (int q = 0; q < 10; ++q) {
        float4 o = make_float4(acc[q * 4], acc[q * 4 + 1], acc[q * 4 + 2], acc[q * 4 + 3]);
        *(float4*)(out + (size_t)node * NCLS + q * 4) = o;
    }
}

// ---------------- host ----------------
extern "C" void kernel_launch(void* const* d_in, const int* in_sizes, int n_in,
                              void* d_out, int out_size) {
    const float* x = nullptr;
    const float* W1 = nullptr;
    const float* b1 = nullptr;
    const float* W2 = nullptr;
    const float* b2 = nullptr;
    const float* beta2 = nullptr;
    const void* ei = nullptr;
    int xsz = 0, esz = 0;

    for (int i = 0; i < n_in; ++i) {
        int sz = in_sizes[i];
        if (sz == NMAX * KIN)            { x = (const float*)d_in[i]; xsz = sz; }
        else if (sz == KIN * HID)        W1 = (const float*)d_in[i];
        else if (sz == HID)              b1 = (const float*)d_in[i];
        else if (sz == HID * NCLS)       W2 = (const float*)d_in[i];
        else if (sz == NCLS)             b2 = (const float*)d_in[i];
        else if (sz == 1)                beta2 = (const float*)d_in[i];
        else if (sz == 2 * EMAX)         { ei = d_in[i]; esz = sz; }
    }
    // positional fallback (dict order: x, W1, b1, W2, b2, beta2, edge_index)
    if (!x || !W1 || !b1 || !W2 || !b2 || !beta2 || !ei) {
        x = (const float*)d_in[0]; xsz = in_sizes[0];
        W1 = (const float*)d_in[1]; b1 = (const float*)d_in[2];
        W2 = (const float*)d_in[3]; b2 = (const float*)d_in[4];
        beta2 = (const float*)d_in[5];
        ei = d_in[6]; esz = in_sizes[6];
    }

    const int n = xsz / KIN;      // 100000
    const int E = esz / 2;        // 1700000
    const int nb = (n + 1023) / 1024;

    k_detect<<<1, 32>>>((const int*)ei);

    k_gemm1<<<(n + 127) / 128, 256>>>(x, W1, b1, n);
    k_norm<<<(n * 8 + 255) / 256, 256>>>(n, 0);

    k_zero<<<(n + 255) / 256, 256>>>(n);
    k_hist<<<2048, 256>>>(ei, E);
    k_scan1<<<nb, 1024>>>(n);
    k_scan2<<<1, 256>>>(nb);
    k_scan3<<<nb, 1024>>>(n);
    k_cursor<<<nb, 1024>>>(n);
    k_scatter<<<2048, 256>>>(ei, E);

    k_conv<<<(n + 7) / 8, 256>>>(n, nullptr, 0);   // prop1: beta = 1, h1 -> h2
    k_norm<<<(n * 8 + 255) / 256, 256>>>(n, 1);
    k_conv<<<(n + 7) / 8, 256>>>(n, beta2, 1);     // prop2: beta = beta2, h2 -> h1

    k_gemm2<<<(n + 127) / 128, 128>>>(W2, b2, (float*)d_out, n);
    (void)out_size;
}